// round 14
// baseline (speedup 1.0000x reference)
#include <cuda_runtime.h>
#include <cuda_fp16.h>
#include <math.h>

// ---------------- problem constants ----------------
#define BS 8
#define NQ 900
#define DM 256
#define NH 8
#define NL 3
#define NP 4
#define DH 32
#define SUMHW 21504           // 128*128 + 64*64 + 32*32
#define NOFF 192              // NH*NL*NP*2
#define NATT 96               // NH*NL*NP
#define QS  (NOFF + NATT)     // 288

// ---------------- scratch ----------------
__device__ float  g_value[(size_t)BS * SUMHW * DM];   // 176 MB
__device__ float  g_qproj[(size_t)BS * NQ * QS];      // 8.3 MB
__device__ float  g_acc[(size_t)BS * NQ * DM];
__device__ float  g_wcat[DM * QS];
__device__ float  g_bcat[QS];
__device__ __half g_wvalT_h[DM * DM];                 // W_val^T in fp16, [n][k]

// ---------------- ptx helpers ----------------
__device__ __forceinline__ void cp16(unsigned dst, const void* src) {
    asm volatile("cp.async.cg.shared.global [%0], [%1], 16;\n" :: "r"(dst), "l"(src));
}
__device__ __forceinline__ float tf32f(float x) {
    unsigned u;
    asm("cvt.rna.tf32.f32 %0, %1;\n" : "=r"(u) : "f"(x));
    return __uint_as_float(u);
}
__device__ __forceinline__ float4 tf32f4(float4 v) {
    v.x = tf32f(v.x); v.y = tf32f(v.y); v.z = tf32f(v.z); v.w = tf32f(v.w);
    return v;
}
__device__ __forceinline__ void mma_tf32(float c[4], const unsigned a[4],
                                         unsigned b0, unsigned b1) {
    asm volatile(
        "mma.sync.aligned.m16n8k8.row.col.f32.tf32.tf32.f32 "
        "{%0,%1,%2,%3}, {%4,%5,%6,%7}, {%8,%9}, {%0,%1,%2,%3};\n"
        : "+f"(c[0]), "+f"(c[1]), "+f"(c[2]), "+f"(c[3])
        : "r"(a[0]), "r"(a[1]), "r"(a[2]), "r"(a[3]), "r"(b0), "r"(b1));
}
__device__ __forceinline__ void mma_f16(float c[4], const unsigned a[4],
                                        unsigned b0, unsigned b1) {
    asm volatile(
        "mma.sync.aligned.m16n8k16.row.col.f32.f16.f16.f32 "
        "{%0,%1,%2,%3}, {%4,%5,%6,%7}, {%8,%9}, {%0,%1,%2,%3};\n"
        : "+f"(c[0]), "+f"(c[1]), "+f"(c[2]), "+f"(c[3])
        : "r"(a[0]), "r"(a[1]), "r"(a[2]), "r"(a[3]), "r"(b0), "r"(b1));
}
__device__ __forceinline__ void ldsm4(unsigned& r0, unsigned& r1, unsigned& r2,
                                      unsigned& r3, unsigned addr) {
    asm volatile("ldmatrix.sync.aligned.m8n8.x4.shared.b16 {%0,%1,%2,%3}, [%4];"
                 : "=r"(r0), "=r"(r1), "=r"(r2), "=r"(r3) : "r"(addr));
}

// smem swizzles (float units) for the tf32 GEMM
__device__ __forceinline__ int asw(int m, int k)    { return m * 32  + (k ^ ((m & 7) << 2)); }
__device__ __forceinline__ int bsw128(int k, int n) { return k * 128 + (n ^ ((k & 3) << 3)); }
__device__ __forceinline__ void cvt4(float* p) {
    *reinterpret_cast<float4*>(p) = tf32f4(*reinterpret_cast<float4*>(p));
}

// pack 8 floats -> 8 fp16 in a uint4
__device__ __forceinline__ uint4 pack8h(const float* f) {
    uint4 r;
    __half2 h;
    h = __floats2half2_rn(f[0], f[1]); r.x = *reinterpret_cast<unsigned*>(&h);
    h = __floats2half2_rn(f[2], f[3]); r.y = *reinterpret_cast<unsigned*>(&h);
    h = __floats2half2_rn(f[4], f[5]); r.z = *reinterpret_cast<unsigned*>(&h);
    h = __floats2half2_rn(f[6], f[7]); r.w = *reinterpret_cast<unsigned*>(&h);
    return r;
}

// ============ fp16 value GEMM v5: BM=128, BN=128, 128 thr, warp 64x64 ======
// 4 warps (2m x 2n), 2 CTAs/SM for cross-CTA latency hiding.
// 3-stage pipeline, one __syncthreads per k-tile.
// Smem rows of 64B (32 halves), 16B-chunk swizzle c ^= (row>>1)&3.
#define AST5 8192
#define BST5 8192
__global__ __launch_bounds__(128, 2) void gemm_f16_val5(
    const float* __restrict__ A, const __half* __restrict__ Bt,
    const float* __restrict__ bias, float* __restrict__ C)
{
    extern __shared__ char smem[];
    char* Asm = smem;                        // [3][8192]   (128 x 32 halves)
    char* Bsm = smem + 3 * AST5;             // [3][8192]   (128 x 32 halves)
    const unsigned sA = (unsigned)__cvta_generic_to_shared(Asm);
    const unsigned sB = (unsigned)__cvta_generic_to_shared(Bsm);

    const int tid = threadIdx.x;
    const int wid = tid >> 5, lane = tid & 31;
    const int g = lane >> 2, t4 = lane & 3;
    const int bm = blockIdx.y * 128;
    const int bn = blockIdx.x * 128;
    const int warp_m = (wid >> 1) * 64;      // 0,64
    const int warp_n = (wid & 1) * 64;       // 0,64

    // ldmatrix lane geometry
    const int a_row0 = warp_m + (lane & 7) + ((lane >> 3) & 1) * 8;  // +16 per mi
    const int a_csel = lane >> 4;
    const int a_rsw  = (a_row0 >> 1) & 3;    // invariant under +16
    const int b_sel  = lane >> 3;
    const int b_row0 = warp_n + (b_sel >> 1) * 8 + (lane & 7);       // +16 per j
    const int b_cadd = b_sel & 1;
    const int b_rsw  = (b_row0 >> 1) & 3;

    // staging: 1 thread per row (128 rows, 128 threads)
    const int lm  = tid;
    const int ssw = (lm >> 1) & 3;

    float4 ra[8];                            // full A row chunk (32 floats)

    auto ldgA = [&](int t) {
        const float* Ag = A + (size_t)(bm + lm) * 256 + t * 32;
#pragma unroll
        for (int p = 0; p < 8; p++)
            ra[p] = *reinterpret_cast<const float4*>(Ag + p * 4);
    };
    auto stsA = [&](int s) {
        char* base = Asm + s * AST5 + lm * 64;
        *reinterpret_cast<uint4*>(base + ((0 ^ ssw) << 4)) = pack8h(&ra[0].x);
        *reinterpret_cast<uint4*>(base + ((1 ^ ssw) << 4)) = pack8h(&ra[2].x);
        *reinterpret_cast<uint4*>(base + ((2 ^ ssw) << 4)) = pack8h(&ra[4].x);
        *reinterpret_cast<uint4*>(base + ((3 ^ ssw) << 4)) = pack8h(&ra[6].x);
    };
    auto cpB = [&](int t, int s) {
        const __half* Bg = Bt + (size_t)(bn + lm) * 256 + t * 32;
        unsigned base = sB + s * BST5 + lm * 64;
#pragma unroll
        for (int c = 0; c < 4; c++)
            cp16(base + ((c ^ ssw) << 4), Bg + c * 8);
        asm volatile("cp.async.commit_group;\n");
    };

    float c[4][8][4];
#pragma unroll
    for (int mi = 0; mi < 4; mi++)
#pragma unroll
        for (int nj = 0; nj < 8; nj++)
#pragma unroll
            for (int r = 0; r < 4; r++) c[mi][nj][r] = 0.f;

    // ---- prologue ----
    ldgA(0);
    cpB(0, 0);
    cpB(1, 1);
    stsA(0);

    int sbuf = 0;                            // buffer index = t % 3
#pragma unroll 1
    for (int t = 0; t < 8; t++) {
        if (t < 7) asm volatile("cp.async.wait_group 1;\n" ::: "memory");
        else       asm volatile("cp.async.wait_group 0;\n" ::: "memory");
        __syncthreads();   // publish stsA(t); readers of reused buffers done

        const int nbuf = (sbuf + 1 < 3) ? sbuf + 1 : 0;
        const int n2buf = (nbuf + 1 < 3) ? nbuf + 1 : 0;

        if (t + 1 < 8) ldgA(t + 1);          // hide LDG under compute
        if (t + 2 < 8) cpB(t + 2, n2buf);    // buf (t+2)%3: readers past barrier

        const unsigned aB = sA + sbuf * AST5;
        const unsigned bB = sB + sbuf * BST5;

#pragma unroll
        for (int kk = 0; kk < 2; kk++) {
            const int c0 = 2 * kk;
            unsigned a[4][4];
#pragma unroll
            for (int mi = 0; mi < 4; mi++) {
                const int row = a_row0 + mi * 16;
                ldsm4(a[mi][0], a[mi][1], a[mi][2], a[mi][3],
                      aB + row * 64 + (((c0 + a_csel) ^ a_rsw) << 4));
            }
            unsigned b[4][4];
#pragma unroll
            for (int j = 0; j < 4; j++) {
                const int nrow = b_row0 + j * 16;
                ldsm4(b[j][0], b[j][1], b[j][2], b[j][3],
                      bB + nrow * 64 + (((c0 + b_cadd) ^ b_rsw) << 4));
            }
#pragma unroll
            for (int j = 0; j < 4; j++)
#pragma unroll
                for (int mi = 0; mi < 4; mi++) {
                    mma_f16(c[mi][2 * j],     a[mi], b[j][0], b[j][1]);
                    mma_f16(c[mi][2 * j + 1], a[mi], b[j][2], b[j][3]);
                }
        }

        if (t + 1 < 8) stsA(nbuf);           // buf (t+1)%3: last read at t-2
        sbuf = nbuf;
    }

    // ---- epilogue: bias + float2 stores ----
#pragma unroll
    for (int mi = 0; mi < 4; mi++) {
        const int r0 = bm + warp_m + mi * 16 + g;
#pragma unroll
        for (int nj = 0; nj < 8; nj++) {
            const int col = bn + warp_n + nj * 8 + 2 * t4;
            const float bx = bias[col], by = bias[col + 1];
            float2 v0 = make_float2(c[mi][nj][0] + bx, c[mi][nj][1] + by);
            float2 v1 = make_float2(c[mi][nj][2] + bx, c[mi][nj][3] + by);
            *reinterpret_cast<float2*>(C + (size_t)r0 * 256 + col) = v0;
            *reinterpret_cast<float2*>(C + (size_t)(r0 + 8) * 256 + col) = v1;
        }
    }
}

// ---------------- W_val transpose + fp16 convert (tiny prep) ---------------
__global__ void transpose_half(const float* __restrict__ W, __half* __restrict__ Wt)
{
    int i = blockIdx.x * blockDim.x + threadIdx.x;   // i = n*256 + k
    if (i < DM * DM) {
        int n = i >> 8, k = i & 255;
        Wt[i] = __float2half(W[k * DM + n]);
    }
}

// ============ guarded TF32 GEMM (q-side / out projections) ================
__global__ __launch_bounds__(256, 2) void gemm_tf32_g(
    const float* __restrict__ A, const float* __restrict__ B,
    const float* __restrict__ bias, float* __restrict__ C,
    int M, int N, int K)
{
    extern __shared__ float sm[];
    float* As = sm;          // [2][4096]
    float* Bs = sm + 8192;   // [2][4096]

    const int tid = threadIdx.x;
    const int wid = tid >> 5, lane = tid & 31;
    const int g = lane >> 2, t4 = lane & 3;
    const int bm = blockIdx.y * 128;
    const int bn = blockIdx.x * 128;
    const int warp_m = (wid >> 1) * 32;
    const int warp_n = (wid & 1) * 64;

    const unsigned smA = (unsigned)__cvta_generic_to_shared(As);
    const unsigned smB = (unsigned)__cvta_generic_to_shared(Bs);

    float c[2][8][4];
#pragma unroll
    for (int mi = 0; mi < 2; mi++)
#pragma unroll
        for (int nj = 0; nj < 8; nj++)
#pragma unroll
            for (int r = 0; r < 4; r++) c[mi][nj][r] = 0.f;

    const int nT = K / 32;

    auto load_stage = [&](int t, int s) {
#pragma unroll
        for (int p = 0; p < 4; p++) {
            int ci = p * 256 + tid;
            int m = ci >> 3, k4 = (ci & 7) << 2;
            int gr = bm + m; if (gr > M - 1) gr = M - 1;
            cp16(smA + (unsigned)(s * 4096 + asw(m, k4)) * 4u,
                 A + (size_t)gr * K + t * 32 + k4);
        }
#pragma unroll
        for (int p = 0; p < 4; p++) {
            int ci = p * 256 + tid;
            int k = ci >> 5, n4 = (ci & 31) << 2;
            int gc = bn + n4; if (gc > N - 4) gc = N - 4;
            cp16(smB + (unsigned)(s * 4096 + bsw128(k, n4)) * 4u,
                 B + (size_t)(t * 32 + k) * N + gc);
        }
    };

    load_stage(0, 0);
    asm volatile("cp.async.commit_group;\n");

#pragma unroll 1
    for (int t = 0; t < nT; t++) {
        if (t + 1 < nT) {
            load_stage(t + 1, (t + 1) & 1);
            asm volatile("cp.async.commit_group;\n");
            asm volatile("cp.async.wait_group 1;\n");
        } else {
            asm volatile("cp.async.wait_group 0;\n");
        }
        __syncthreads();

        float* as = As + (t & 1) * 4096;
        float* bs = Bs + (t & 1) * 4096;

#pragma unroll
        for (int p = 0; p < 4; p++) cvt4(as + (p * 256 + tid) * 4);
#pragma unroll
        for (int p = 0; p < 4; p++) cvt4(bs + (p * 256 + tid) * 4);
        __syncthreads();

#pragma unroll
        for (int kk = 0; kk < 32; kk += 8) {
            const int kA = kk + t4;
            unsigned a[2][4];
#pragma unroll
            for (int mi = 0; mi < 2; mi++) {
                const int r0 = warp_m + mi * 16 + g;
                const int r1 = r0 + 8;
                a[mi][0] = __float_as_uint(as[asw(r0, kA)]);
                a[mi][1] = __float_as_uint(as[asw(r1, kA)]);
                a[mi][2] = __float_as_uint(as[asw(r0, kA + 4)]);
                a[mi][3] = __float_as_uint(as[asw(r1, kA + 4)]);
            }
#pragma unroll
            for (int nj = 0; nj < 8; nj++) {
                const int col = warp_n + nj * 8 + g;
                unsigned b0 = __float_as_uint(bs[bsw128(kA, col)]);
                unsigned b1 = __float_as_uint(bs[bsw128(kA + 4, col)]);
                mma_tf32(c[0][nj], a[0], b0, b1);
                mma_tf32(c[1][nj], a[1], b0, b1);
            }
        }
        __syncthreads();
    }

#pragma unroll
    for (int mi = 0; mi < 2; mi++) {
        const int r0 = bm + warp_m + mi * 16 + g;
#pragma unroll
        for (int nj = 0; nj < 8; nj++) {
            const int col = bn + warp_n + nj * 8 + 2 * t4;
            if (col + 1 < N) {
                const float bx = bias[col], by = bias[col + 1];
                if (r0 < M) {
                    float2 v0 = make_float2(c[mi][nj][0] + bx, c[mi][nj][1] + by);
                    *reinterpret_cast<float2*>(C + (size_t)r0 * N + col) = v0;
                }
                if (r0 + 8 < M) {
                    float2 v1 = make_float2(c[mi][nj][2] + bx, c[mi][nj][3] + by);
                    *reinterpret_cast<float2*>(C + (size_t)(r0 + 8) * N + col) = v1;
                }
            }
        }
    }
}

// ---------------- concat W_off|W_attn --------------------------------------
__global__ void concat_w(const float* __restrict__ W_off, const float* __restrict__ b_off,
                         const float* __restrict__ W_attn, const float* __restrict__ b_attn,
                         float* __restrict__ Wcat, float* __restrict__ bcat)
{
    int i = blockIdx.x * blockDim.x + threadIdx.x;
    if (i < DM * QS) {
        int r = i / QS, col = i % QS;
        Wcat[i] = (col < NOFF) ? W_off[r * NOFF + col] : W_attn[r * NATT + col - NOFF];
    }
    if (i < QS)
        bcat[i] = (i < NOFF) ? b_off[i] : b_attn[i - NOFF];
}

// ---------------- sampling v2: lane-parallel point precompute --------------
__global__ __launch_bounds__(256) void msda_sample2(
    const float* __restrict__ refp_g,   // [BS, NQ, NL, 2]
    const float* __restrict__ qproj_g,  // [BS, NQ, QS]  (off | att)
    const float* __restrict__ value_g,  // [BS, SUMHW, DM]
    float* __restrict__ acc_g)          // [BS, NQ, DM]
{
    __shared__ float sdata[8][96];

    const int wlocal = threadIdx.x >> 5;
    const int gwarp  = (blockIdx.x * blockDim.x + threadIdx.x) >> 5;
    const int lane   = threadIdx.x & 31;
    if (gwarp >= BS * NQ * NH) return;

    const int h  = gwarp & (NH - 1);
    const int bq = gwarp >> 3;
    const int b  = bq / NQ;

    float* sp = sdata[wlocal];

    // ---- phase 1: lanes 0-11 compute one point each ----
    {
        const int i = lane;
        float v = -INFINITY;
        if (i < 12) v = qproj_g[(size_t)bq * QS + NOFF + h * 12 + i];
        float mx = v;
#pragma unroll
        for (int o = 8; o; o >>= 1) mx = fmaxf(mx, __shfl_xor_sync(0xffffffffu, mx, o, 16));
        float e = (i < 12) ? expf(v - mx) : 0.f;
        float s = e;
#pragma unroll
        for (int o = 8; o; o >>= 1) s += __shfl_xor_sync(0xffffffffu, s, o, 16);

        if (i < 12) {
            const float aw = e / s;
            const int l   = i >> 2;
            const int Dim = 128 >> l;                    // 128,64,32
            const int st  = (l == 0) ? 0 : (l == 1) ? 16384 : 20480;
            const float ref_x = refp_g[(size_t)bq * (NL * 2) + 2 * l];
            const float ref_y = refp_g[(size_t)bq * (NL * 2) + 2 * l + 1];
            const float ox = qproj_g[(size_t)bq * QS + h * 24 + 2 * i];
            const float oy = qproj_g[(size_t)bq * QS + h * 24 + 2 * i + 1];

            const float px = ref_x * (float)Dim + ox - 0.5f;
            const float py = ref_y * (float)Dim + oy - 0.5f;
            const float fx = floorf(px), fy = floorf(py);
            const float lx = px - fx, ly = py - fy;
            const int x0 = (int)fx, y0 = (int)fy;

            const bool vx0 = ((unsigned)x0       < (unsigned)Dim);
            const bool vx1 = ((unsigned)(x0 + 1) < (unsigned)Dim);
            const bool vy0 = ((unsigned)y0       < (unsigned)Dim);
            const bool vy1 = ((unsigned)(y0 + 1) < (unsigned)Dim);

            const int cx0 = min(max(x0, 0), Dim - 1);
            const int cx1 = min(max(x0 + 1, 0), Dim - 1);
            const int cy0 = min(max(y0, 0), Dim - 1);
            const int cy1 = min(max(y0 + 1, 0), Dim - 1);

            sp[i * 8 + 0] = (vx0 && vy0) ? aw * (1.f - lx) * (1.f - ly) : 0.f;
            sp[i * 8 + 1] = (vx1 && vy0) ? aw * lx * (1.f - ly) : 0.f;
            sp[i * 8 + 2] = (vx0 && vy1) ? aw * (1.f - lx) * ly : 0.f;
            sp[i * 8 + 3] = (vx1 && vy1) ? aw * lx * ly : 0.f;
            sp[i * 8 + 4] = __int_as_float((st + cy0 * Dim + cx0) * DM);
            sp[i * 8 + 5] = __int_as_float((st + cy0 * Dim + cx1) * DM);
            sp[i * 8 + 6] = __int_as_float((st + cy1 * Dim + cx0) * DM);
            sp[i * 8 + 7] = __int_as_float((st + cy1 * Dim + cx1) * DM);
        }
    }
    __syncwarp();

    // ---- phase 2: all lanes gather 12 points x 4 taps ----
    const float* vb = value_g + (size_t)b * SUMHW * DM + h * DH + lane;
    float a0 = 0.f, a1 = 0.f;
#pragma unroll
    for (int i = 0; i < 12; i++) {
        const float m00 = sp[i * 8 + 0];
        const float m10 = sp[i * 8 + 1];
        const float m01 = sp[i * 8 + 2];
        const float m11 = sp[i * 8 + 3];
        const int i00 = __float_as_int(sp[i * 8 + 4]);
        const int i10 = __float_as_int(sp[i * 8 + 5]);
        const int i01 = __float_as_int(sp[i * 8 + 6]);
        const int i11 = __float_as_int(sp[i * 8 + 7]);
        a0 = fmaf(m00, vb[i00], a0);
        a1 = fmaf(m10, vb[i10], a1);
        a0 = fmaf(m01, vb[i01], a0);
        a1 = fmaf(m11, vb[i11], a1);
    }
    acc_g[(size_t)bq * DM + h * DH + lane] = a0 + a1;
}

// ---------------- launch ---------------------------------------------------
extern "C" void kernel_launch(void* const* d_in, const int* in_sizes, int n_in,
                              void* d_out, int out_size)
{
    const float* query  = (const float*)d_in[0];
    const float* refpts = (const float*)d_in[1];
    const float* inflat = (const float*)d_in[2];
    const float* W_off  = (const float*)d_in[5];
    const float* b_off  = (const float*)d_in[6];
    const float* W_attn = (const float*)d_in[7];
    const float* b_attn = (const float*)d_in[8];
    const float* W_val  = (const float*)d_in[9];
    const float* b_val  = (const float*)d_in[10];
    const float* W_out  = (const float*)d_in[11];
    const float* b_out  = (const float*)d_in[12];
    float* out = (float*)d_out;

    float *value, *qproj, *acc, *wcat, *bcat;
    __half* wvalT;
    cudaGetSymbolAddress((void**)&value, g_value);
    cudaGetSymbolAddress((void**)&qproj, g_qproj);
    cudaGetSymbolAddress((void**)&acc,   g_acc);
    cudaGetSymbolAddress((void**)&wcat,  g_wcat);
    cudaGetSymbolAddress((void**)&bcat,  g_bcat);
    cudaGetSymbolAddress((void**)&wvalT, g_wvalT_h);

    const int MQ = BS * NQ;          // 7200
    const int MV = BS * SUMHW;       // 172032

    const int smem_g = 2 * 2 * 4096 * (int)sizeof(float);        // 64 KB
    const int smem_v = 3 * (AST5 + BST5);                        // 49152 B
    cudaFuncSetAttribute(gemm_tf32_g,   cudaFuncAttributeMaxDynamicSharedMemorySize, smem_g);
    cudaFuncSetAttribute(gemm_f16_val5, cudaFuncAttributeMaxDynamicSharedMemorySize, smem_v);

    // 0) weight prep (tiny)
    concat_w<<<(DM * QS + 255) / 256, 256>>>(W_off, b_off, W_attn, b_attn, wcat, bcat);
    transpose_half<<<(DM * DM + 255) / 256, 256>>>(W_val, wvalT);

    // 1) fused q projection: [7200,256] @ [256,288] -> qproj (off | att)
    gemm_tf32_g<<<dim3(3, (MQ + 127) / 128), 256, smem_g>>>(
        query, wcat, bcat, qproj, MQ, QS, DM);

    // 2) value projection (fp16, 128-thr CTAs, 2/SM): [172032,256] @ [256,256]
    gemm_f16_val5<<<dim3(2, MV / 128), 128, smem_v>>>(inflat, wvalT, b_val, value);

    // 3) sampling (lane-parallel precompute)
    {
        const int warps = BS * NQ * NH;
        const int blocks = (warps * 32 + 255) / 256;
        msda_sample2<<<blocks, 256>>>(refpts, qproj, value, acc);
    }

    // 4) output projection: [7200,256] @ [256,256] -> d_out
    gemm_tf32_g<<<dim3(2, (MQ + 127) / 128), 256, smem_g>>>(
        acc, W_out, b_out, out, MQ, DM, DM);
}

// round 15
// speedup vs baseline: 1.2129x; 1.2129x over previous
#include <cuda_runtime.h>
#include <cuda_fp16.h>
#include <math.h>

// ---------------- problem constants ----------------
#define BS 8
#define NQ 900
#define DM 256
#define NH 8
#define NL 3
#define NP 4
#define DH 32
#define SUMHW 21504           // 128*128 + 64*64 + 32*32
#define NOFF 192              // NH*NL*NP*2
#define NATT 96               // NH*NL*NP
#define QS  (NOFF + NATT)     // 288

// ---------------- scratch ----------------
__device__ float  g_value[(size_t)BS * SUMHW * DM];   // 176 MB
__device__ float  g_qproj[(size_t)BS * NQ * QS];      // 8.3 MB
__device__ float  g_acc[(size_t)BS * NQ * DM];
__device__ float  g_bcat[QS];
__device__ __half g_wvalT_h[DM * DM];                 // W_val^T fp16 [n][k]
__device__ __half g_wcatT_h[QS * DM];                 // (W_off|W_attn)^T fp16 [n][k]
__device__ __half g_woutT_h[DM * DM];                 // W_out^T fp16 [n][k]

// ---------------- ptx helpers ----------------
__device__ __forceinline__ void cp16(unsigned dst, const void* src) {
    asm volatile("cp.async.cg.shared.global [%0], [%1], 16;\n" :: "r"(dst), "l"(src));
}
__device__ __forceinline__ void mma_f16(float c[4], const unsigned a[4],
                                        unsigned b0, unsigned b1) {
    asm volatile(
        "mma.sync.aligned.m16n8k16.row.col.f32.f16.f16.f32 "
        "{%0,%1,%2,%3}, {%4,%5,%6,%7}, {%8,%9}, {%0,%1,%2,%3};\n"
        : "+f"(c[0]), "+f"(c[1]), "+f"(c[2]), "+f"(c[3])
        : "r"(a[0]), "r"(a[1]), "r"(a[2]), "r"(a[3]), "r"(b0), "r"(b1));
}
__device__ __forceinline__ void ldsm4(unsigned& r0, unsigned& r1, unsigned& r2,
                                      unsigned& r3, unsigned addr) {
    asm volatile("ldmatrix.sync.aligned.m8n8.x4.shared.b16 {%0,%1,%2,%3}, [%4];"
                 : "=r"(r0), "=r"(r1), "=r"(r2), "=r"(r3) : "r"(addr));
}
// pack 8 floats -> 8 fp16 in a uint4
__device__ __forceinline__ uint4 pack8h(const float* f) {
    uint4 r;
    __half2 h;
    h = __floats2half2_rn(f[0], f[1]); r.x = *reinterpret_cast<unsigned*>(&h);
    h = __floats2half2_rn(f[2], f[3]); r.y = *reinterpret_cast<unsigned*>(&h);
    h = __floats2half2_rn(f[4], f[5]); r.z = *reinterpret_cast<unsigned*>(&h);
    h = __floats2half2_rn(f[6], f[7]); r.w = *reinterpret_cast<unsigned*>(&h);
    return r;
}

// ============ fp16 value GEMM (v3, proven 116.8us): BM=128, BN=128 =========
// 256 thr, 8 warps, warp tile 32x64, m16n8k16 + ldmatrix.
// Smem rows of 64B (32 halves), 16B-chunk swizzle c ^= (row>>1)&3.
__global__ __launch_bounds__(256, 2) void gemm_f16_val(
    const float* __restrict__ A, const __half* __restrict__ Bt,
    const float* __restrict__ bias, float* __restrict__ C)
{
    extern __shared__ char smem[];
    char* Asm = smem;                       // [2][8192]
    char* Bsm = smem + 16384;               // [2][8192]
    const unsigned sA = (unsigned)__cvta_generic_to_shared(Asm);
    const unsigned sB = (unsigned)__cvta_generic_to_shared(Bsm);

    const int tid = threadIdx.x;
    const int wid = tid >> 5, lane = tid & 31;
    const int g = lane >> 2, t4 = lane & 3;
    const int bm = blockIdx.y * 128;
    const int bn = blockIdx.x * 128;
    const int warp_m = (wid >> 1) * 32;     // 0,32,64,96
    const int warp_n = (wid & 1) * 64;      // 0,64

    const int a_row0 = warp_m + (lane & 7) + ((lane >> 3) & 1) * 8;
    const int a_csel = lane >> 4;
    const int a_rsw  = (a_row0 >> 1) & 3;
    const int b_sel  = lane >> 3;
    const int b_row0 = warp_n + (b_sel >> 1) * 8 + (lane & 7);
    const int b_cadd = b_sel & 1;
    const int b_rsw  = (b_row0 >> 1) & 3;

    const int lm = tid >> 1;
    const int cb = (tid & 1) * 2;
    const int lk = (tid & 1) * 16;

    float4 ra[4];

    auto ldgA = [&](int t) {
        const float* Ag = A + (size_t)(bm + lm) * 256 + t * 32 + lk;
#pragma unroll
        for (int p = 0; p < 4; p++)
            ra[p] = *reinterpret_cast<const float4*>(Ag + p * 4);
    };
    auto stsA = [&](int s) {
        const int sw = (lm >> 1) & 3;
        char* base = Asm + s * 8192 + lm * 64;
        *reinterpret_cast<uint4*>(base + (((cb)     ^ sw) << 4)) = pack8h(&ra[0].x);
        *reinterpret_cast<uint4*>(base + (((cb + 1) ^ sw) << 4)) = pack8h(&ra[2].x);
    };
    auto cpB = [&](int t, int s) {
        const __half* Bg = Bt + (size_t)(bn + lm) * 256 + t * 32 + cb * 8;
        const int sw = (lm >> 1) & 3;
        unsigned base = sB + s * 8192 + lm * 64;
        cp16(base + (((cb)     ^ sw) << 4), Bg);
        cp16(base + (((cb + 1) ^ sw) << 4), Bg + 8);
        asm volatile("cp.async.commit_group;\n");
    };

    float c[2][8][4];
#pragma unroll
    for (int mi = 0; mi < 2; mi++)
#pragma unroll
        for (int nj = 0; nj < 8; nj++)
#pragma unroll
            for (int r = 0; r < 4; r++) c[mi][nj][r] = 0.f;

    cpB(0, 0);
    ldgA(0);
    stsA(0);

#pragma unroll 1
    for (int t = 0; t < 8; t++) {
        if (t + 1 < 8) {
            ldgA(t + 1);
            cpB(t + 1, (t + 1) & 1);
            asm volatile("cp.async.wait_group 1;\n" ::: "memory");
        } else {
            asm volatile("cp.async.wait_group 0;\n" ::: "memory");
        }
        __syncthreads();

        const unsigned aB = sA + (t & 1) * 8192;
        const unsigned bB = sB + (t & 1) * 8192;

#pragma unroll
        for (int kk = 0; kk < 2; kk++) {
            const int c0 = 2 * kk;
            unsigned a[2][4];
#pragma unroll
            for (int mi = 0; mi < 2; mi++) {
                const int row = a_row0 + mi * 16;
                ldsm4(a[mi][0], a[mi][1], a[mi][2], a[mi][3],
                      aB + row * 64 + (((c0 + a_csel) ^ a_rsw) << 4));
            }
            unsigned b[4][4];
#pragma unroll
            for (int j = 0; j < 4; j++) {
                const int nrow = b_row0 + j * 16;
                ldsm4(b[j][0], b[j][1], b[j][2], b[j][3],
                      bB + nrow * 64 + (((c0 + b_cadd) ^ b_rsw) << 4));
            }
#pragma unroll
            for (int j = 0; j < 4; j++) {
                mma_f16(c[0][2 * j],     a[0], b[j][0], b[j][1]);
                mma_f16(c[1][2 * j],     a[1], b[j][0], b[j][1]);
                mma_f16(c[0][2 * j + 1], a[0], b[j][2], b[j][3]);
                mma_f16(c[1][2 * j + 1], a[1], b[j][2], b[j][3]);
            }
        }

        if (t + 1 < 8) {
            __syncthreads();
            stsA((t + 1) & 1);
        }
    }

#pragma unroll
    for (int mi = 0; mi < 2; mi++) {
        const int r0 = bm + warp_m + mi * 16 + g;
#pragma unroll
        for (int nj = 0; nj < 8; nj++) {
            const int col = bn + warp_n + nj * 8 + 2 * t4;
            const float bx = bias[col], by = bias[col + 1];
            float2 v0 = make_float2(c[mi][nj][0] + bx, c[mi][nj][1] + by);
            float2 v1 = make_float2(c[mi][nj][2] + bx, c[mi][nj][3] + by);
            *reinterpret_cast<float2*>(C + (size_t)r0 * 256 + col) = v0;
            *reinterpret_cast<float2*>(C + (size_t)(r0 + 8) * 256 + col) = v1;
        }
    }
}

// ============ generalized fp16 GEMM (q-side / out projections) =============
// C[M,N] = A[M,K=256] @ Bt^T + bias, Bt fp16 [N][256].  Same tiling as above;
// row/col clamped loads, guarded stores.  K fixed at 256.
__global__ __launch_bounds__(256) void gemm_f16_g(
    const float* __restrict__ A, const __half* __restrict__ Bt,
    const float* __restrict__ bias, float* __restrict__ C,
    int M, int N)
{
    extern __shared__ char smem[];
    char* Asm = smem;
    char* Bsm = smem + 16384;
    const unsigned sA = (unsigned)__cvta_generic_to_shared(Asm);
    const unsigned sB = (unsigned)__cvta_generic_to_shared(Bsm);

    const int tid = threadIdx.x;
    const int wid = tid >> 5, lane = tid & 31;
    const int g = lane >> 2, t4 = lane & 3;
    const int bm = blockIdx.y * 128;
    const int bn = blockIdx.x * 128;
    const int warp_m = (wid >> 1) * 32;
    const int warp_n = (wid & 1) * 64;

    const int a_row0 = warp_m + (lane & 7) + ((lane >> 3) & 1) * 8;
    const int a_csel = lane >> 4;
    const int a_rsw  = (a_row0 >> 1) & 3;
    const int b_sel  = lane >> 3;
    const int b_row0 = warp_n + (b_sel >> 1) * 8 + (lane & 7);
    const int b_cadd = b_sel & 1;
    const int b_rsw  = (b_row0 >> 1) & 3;

    const int lm = tid >> 1;
    const int cb = (tid & 1) * 2;
    const int lk = (tid & 1) * 16;

    const int arow = min(bm + lm, M - 1);
    const int brow = min(bn + lm, N - 1);

    float4 ra[4];

    auto ldgA = [&](int t) {
        const float* Ag = A + (size_t)arow * 256 + t * 32 + lk;
#pragma unroll
        for (int p = 0; p < 4; p++)
            ra[p] = *reinterpret_cast<const float4*>(Ag + p * 4);
    };
    auto stsA = [&](int s) {
        const int sw = (lm >> 1) & 3;
        char* base = Asm + s * 8192 + lm * 64;
        *reinterpret_cast<uint4*>(base + (((cb)     ^ sw) << 4)) = pack8h(&ra[0].x);
        *reinterpret_cast<uint4*>(base + (((cb + 1) ^ sw) << 4)) = pack8h(&ra[2].x);
    };
    auto cpB = [&](int t, int s) {
        const __half* Bg = Bt + (size_t)brow * 256 + t * 32 + cb * 8;
        const int sw = (lm >> 1) & 3;
        unsigned base = sB + s * 8192 + lm * 64;
        cp16(base + (((cb)     ^ sw) << 4), Bg);
        cp16(base + (((cb + 1) ^ sw) << 4), Bg + 8);
        asm volatile("cp.async.commit_group;\n");
    };

    float c[2][8][4];
#pragma unroll
    for (int mi = 0; mi < 2; mi++)
#pragma unroll
        for (int nj = 0; nj < 8; nj++)
#pragma unroll
            for (int r = 0; r < 4; r++) c[mi][nj][r] = 0.f;

    cpB(0, 0);
    ldgA(0);
    stsA(0);

#pragma unroll 1
    for (int t = 0; t < 8; t++) {
        if (t + 1 < 8) {
            ldgA(t + 1);
            cpB(t + 1, (t + 1) & 1);
            asm volatile("cp.async.wait_group 1;\n" ::: "memory");
        } else {
            asm volatile("cp.async.wait_group 0;\n" ::: "memory");
        }
        __syncthreads();

        const unsigned aB = sA + (t & 1) * 8192;
        const unsigned bB = sB + (t & 1) * 8192;

#pragma unroll
        for (int kk = 0; kk < 2; kk++) {
            const int c0 = 2 * kk;
            unsigned a[2][4];
#pragma unroll
            for (int mi = 0; mi < 2; mi++) {
                const int row = a_row0 + mi * 16;
                ldsm4(a[mi][0], a[mi][1], a[mi][2], a[mi][3],
                      aB + row * 64 + (((c0 + a_csel) ^ a_rsw) << 4));
            }
            unsigned b[4][4];
#pragma unroll
            for (int j = 0; j < 4; j++) {
                const int nrow = b_row0 + j * 16;
                ldsm4(b[j][0], b[j][1], b[j][2], b[j][3],
                      bB + nrow * 64 + (((c0 + b_cadd) ^ b_rsw) << 4));
            }
#pragma unroll
            for (int j = 0; j < 4; j++) {
                mma_f16(c[0][2 * j],     a[0], b[j][0], b[j][1]);
                mma_f16(c[1][2 * j],     a[1], b[j][0], b[j][1]);
                mma_f16(c[0][2 * j + 1], a[0], b[j][2], b[j][3]);
                mma_f16(c[1][2 * j + 1], a[1], b[j][2], b[j][3]);
            }
        }

        if (t + 1 < 8) {
            __syncthreads();
            stsA((t + 1) & 1);
        }
    }

#pragma unroll
    for (int mi = 0; mi < 2; mi++) {
        const int r0 = bm + warp_m + mi * 16 + g;
#pragma unroll
        for (int nj = 0; nj < 8; nj++) {
            const int col = bn + warp_n + nj * 8 + 2 * t4;
            if (col < N) {
                const float bx = bias[col], by = bias[col + 1];
                if (r0 < M) {
                    float2 v0 = make_float2(c[mi][nj][0] + bx, c[mi][nj][1] + by);
                    *reinterpret_cast<float2*>(C + (size_t)r0 * N + col) = v0;
                }
                if (r0 + 8 < M) {
                    float2 v1 = make_float2(c[mi][nj][2] + bx, c[mi][nj][3] + by);
                    *reinterpret_cast<float2*>(C + (size_t)(r0 + 8) * N + col) = v1;
                }
            }
        }
    }
}

// ---------------- weight prep (tiny) ---------------------------------------
// W [256][ncols] fp32 -> Wt [ncols][256] fp16
__global__ void transpose_half_n(const float* __restrict__ W, __half* __restrict__ Wt,
                                 int ncols)
{
    int i = blockIdx.x * blockDim.x + threadIdx.x;   // i = n*256 + k
    if (i < ncols * DM) {
        int n = i >> 8, k = i & 255;
        Wt[i] = __float2half(W[k * ncols + n]);
    }
}
// concat W_off|W_attn transposed -> fp16 [288][256]; bias concat
__global__ void concat_w_t(const float* __restrict__ W_off, const float* __restrict__ b_off,
                           const float* __restrict__ W_attn, const float* __restrict__ b_attn,
                           __half* __restrict__ WcatT, float* __restrict__ bcat)
{
    int i = blockIdx.x * blockDim.x + threadIdx.x;   // i = n*256 + k
    if (i < QS * DM) {
        int n = i >> 8, k = i & 255;
        float v = (n < NOFF) ? W_off[k * NOFF + n] : W_attn[k * NATT + (n - NOFF)];
        WcatT[i] = __float2half(v);
    }
    if (i < QS)
        bcat[i] = (i < NOFF) ? b_off[i] : b_attn[i - NOFF];
}

// ---------------- sampling v2: lane-parallel point precompute --------------
__global__ __launch_bounds__(256) void msda_sample2(
    const float* __restrict__ refp_g,   // [BS, NQ, NL, 2]
    const float* __restrict__ qproj_g,  // [BS, NQ, QS]  (off | att)
    const float* __restrict__ value_g,  // [BS, SUMHW, DM]
    float* __restrict__ acc_g)          // [BS, NQ, DM]
{
    __shared__ float sdata[8][96];

    const int wlocal = threadIdx.x >> 5;
    const int gwarp  = (blockIdx.x * blockDim.x + threadIdx.x) >> 5;
    const int lane   = threadIdx.x & 31;
    if (gwarp >= BS * NQ * NH) return;

    const int h  = gwarp & (NH - 1);
    const int bq = gwarp >> 3;
    const int b  = bq / NQ;

    float* sp = sdata[wlocal];

    {
        const int i = lane;
        float v = -INFINITY;
        if (i < 12) v = qproj_g[(size_t)bq * QS + NOFF + h * 12 + i];
        float mx = v;
#pragma unroll
        for (int o = 8; o; o >>= 1) mx = fmaxf(mx, __shfl_xor_sync(0xffffffffu, mx, o, 16));
        float e = (i < 12) ? expf(v - mx) : 0.f;
        float s = e;
#pragma unroll
        for (int o = 8; o; o >>= 1) s += __shfl_xor_sync(0xffffffffu, s, o, 16);

        if (i < 12) {
            const float aw = e / s;
            const int l   = i >> 2;
            const int Dim = 128 >> l;                    // 128,64,32
            const int st  = (l == 0) ? 0 : (l == 1) ? 16384 : 20480;
            const float ref_x = refp_g[(size_t)bq * (NL * 2) + 2 * l];
            const float ref_y = refp_g[(size_t)bq * (NL * 2) + 2 * l + 1];
            const float ox = qproj_g[(size_t)bq * QS + h * 24 + 2 * i];
            const float oy = qproj_g[(size_t)bq * QS + h * 24 + 2 * i + 1];

            const float px = ref_x * (float)Dim + ox - 0.5f;
            const float py = ref_y * (float)Dim + oy - 0.5f;
            const float fx = floorf(px), fy = floorf(py);
            const float lx = px - fx, ly = py - fy;
            const int x0 = (int)fx, y0 = (int)fy;

            const bool vx0 = ((unsigned)x0       < (unsigned)Dim);
            const bool vx1 = ((unsigned)(x0 + 1) < (unsigned)Dim);
            const bool vy0 = ((unsigned)y0       < (unsigned)Dim);
            const bool vy1 = ((unsigned)(y0 + 1) < (unsigned)Dim);

            const int cx0 = min(max(x0, 0), Dim - 1);
            const int cx1 = min(max(x0 + 1, 0), Dim - 1);
            const int cy0 = min(max(y0, 0), Dim - 1);
            const int cy1 = min(max(y0 + 1, 0), Dim - 1);

            sp[i * 8 + 0] = (vx0 && vy0) ? aw * (1.f - lx) * (1.f - ly) : 0.f;
            sp[i * 8 + 1] = (vx1 && vy0) ? aw * lx * (1.f - ly) : 0.f;
            sp[i * 8 + 2] = (vx0 && vy1) ? aw * (1.f - lx) * ly : 0.f;
            sp[i * 8 + 3] = (vx1 && vy1) ? aw * lx * ly : 0.f;
            sp[i * 8 + 4] = __int_as_float((st + cy0 * Dim + cx0) * DM);
            sp[i * 8 + 5] = __int_as_float((st + cy0 * Dim + cx1) * DM);
            sp[i * 8 + 6] = __int_as_float((st + cy1 * Dim + cx0) * DM);
            sp[i * 8 + 7] = __int_as_float((st + cy1 * Dim + cx1) * DM);
        }
    }
    __syncwarp();

    const float* vb = value_g + (size_t)b * SUMHW * DM + h * DH + lane;
    float a0 = 0.f, a1 = 0.f;
#pragma unroll
    for (int i = 0; i < 12; i++) {
        const float m00 = sp[i * 8 + 0];
        const float m10 = sp[i * 8 + 1];
        const float m01 = sp[i * 8 + 2];
        const float m11 = sp[i * 8 + 3];
        const int i00 = __float_as_int(sp[i * 8 + 4]);
        const int i10 = __float_as_int(sp[i * 8 + 5]);
        const int i01 = __float_as_int(sp[i * 8 + 6]);
        const int i11 = __float_as_int(sp[i * 8 + 7]);
        a0 = fmaf(m00, vb[i00], a0);
        a1 = fmaf(m10, vb[i10], a1);
        a0 = fmaf(m01, vb[i01], a0);
        a1 = fmaf(m11, vb[i11], a1);
    }
    acc_g[(size_t)bq * DM + h * DH + lane] = a0 + a1;
}

// ---------------- launch ---------------------------------------------------
extern "C" void kernel_launch(void* const* d_in, const int* in_sizes, int n_in,
                              void* d_out, int out_size)
{
    const float* query  = (const float*)d_in[0];
    const float* refpts = (const float*)d_in[1];
    const float* inflat = (const float*)d_in[2];
    const float* W_off  = (const float*)d_in[5];
    const float* b_off  = (const float*)d_in[6];
    const float* W_attn = (const float*)d_in[7];
    const float* b_attn = (const float*)d_in[8];
    const float* W_val  = (const float*)d_in[9];
    const float* b_val  = (const float*)d_in[10];
    const float* W_out  = (const float*)d_in[11];
    const float* b_out  = (const float*)d_in[12];
    float* out = (float*)d_out;

    float *value, *qproj, *acc, *bcat;
    __half *wvalT, *wcatT, *woutT;
    cudaGetSymbolAddress((void**)&value, g_value);
    cudaGetSymbolAddress((void**)&qproj, g_qproj);
    cudaGetSymbolAddress((void**)&acc,   g_acc);
    cudaGetSymbolAddress((void**)&bcat,  g_bcat);
    cudaGetSymbolAddress((void**)&wvalT, g_wvalT_h);
    cudaGetSymbolAddress((void**)&wcatT, g_wcatT_h);
    cudaGetSymbolAddress((void**)&woutT, g_woutT_h);

    const int MQ = BS * NQ;          // 7200
    const int MV = BS * SUMHW;       // 172032
    const int smem_v = 32768;        // 32 KB

    cudaFuncSetAttribute(gemm_f16_val, cudaFuncAttributeMaxDynamicSharedMemorySize, smem_v);
    cudaFuncSetAttribute(gemm_f16_g,   cudaFuncAttributeMaxDynamicSharedMemorySize, smem_v);

    // 0) weight prep (tiny)
    concat_w_t<<<(QS * DM + 255) / 256, 256>>>(W_off, b_off, W_attn, b_attn, wcatT, bcat);
    transpose_half_n<<<(DM * DM + 255) / 256, 256>>>(W_val, wvalT, DM);
    transpose_half_n<<<(DM * DM + 255) / 256, 256>>>(W_out, woutT, DM);

    // 1) fused q projection (fp16): [7200,256] @ [256,288] -> qproj
    gemm_f16_g<<<dim3(3, (MQ + 127) / 128), 256, smem_v>>>(
        query, wcatT, bcat, qproj, MQ, QS);

    // 2) value projection (fp16, proven v3): [172032,256] @ [256,256]
    gemm_f16_val<<<dim3(2, MV / 128), 256, smem_v>>>(inflat, wvalT, b_val, value);

    // 3) sampling (lane-parallel precompute)
    {
        const int warps = BS * NQ * NH;
        const int blocks = (warps * 32 + 255) / 256;
        msda_sample2<<<blocks, 256>>>(refpts, qproj, value, acc);
    }

    // 4) output projection (fp16): [7200,256] @ [256,256] -> d_out
    gemm_f16_g<<<dim3(2, (MQ + 127) / 128), 256, smem_v>>>(
        acc, woutT, b_out, out, MQ, DM);
}